// round 6
// baseline (speedup 1.0000x reference)
#include <cuda_runtime.h>
#include <math.h>

#define B_   8
#define S_   4096
#define H_   1024
#define R_   (B_ * H_)
#define CAP  128
// exact threshold in lg2 domain: ln(x)+g > 3.3  <=>  lg2(x)+g/ln2 > 3.3/ln2
#define TAU_LG2   4.7608936f
#define TAU_CHK   4.7610f          /* slightly above: conservative validity check */
#define INV_LN2   1.44269504f
// integer-domain filter constants (superset predicate, slack 0.0875 lg2):
//   pass if (float)as_int(x) > K' - g*C'  with C' = INV_LN2*2^23, K' = (tau2+127-0.0875)*2^23
#define FILT_C   12102202.0f
#define FILT_K   1104556453.0f

// ---------------- device scratch (zero-initialized at load; select restores) ----------------
__device__ float2 g_buf[R_ * CAP];   // survivor (x, g) per row
__device__ int    g_cnt[R_];         // zeroed at init; k_select resets after use
__device__ float  g_pooled[R_];

__device__ __forceinline__ float neg_inf() { return __int_as_float(0xff800000); }

// MUFU-free conservative filter: passes every element whose exact score > TAU_LG2.
__device__ __forceinline__ void flt_test(float x, float g, int r) {
    float xf  = __int2float_rn(__float_as_int(x));   // bit-hack log (x<=0 -> huge negative)
    float rhs = fmaf(g, -FILT_C, FILT_K);
    if (xf > rhs) {
        int p = atomicAdd(&g_cnt[r], 1);
        if (p < CAP) g_buf[r * CAP + p] = make_float2(x, g);
    }
}

// ---------------- 1: streaming filter, 128-bit loads, MUFU-free predicate ----------------
// Block tile: 128 h x 64 s.
// smem layout: sg4[s*32 + (hq ^ (s>>2))]: 2-way max STS conflicts, conflict-free LDS.128.
__global__ __launch_bounds__(256, 6) void k_filter(const float* __restrict__ hidden,
                                                   const float* __restrict__ gumbel) {
    __shared__ float4 sg4[64 * 32];          // 32 KB
    float* sg = (float*)sg4;

    int blk  = blockIdx.x;                   // 0..4095
    int sblk = blk & 63;
    int hblk = (blk >> 6) & 7;
    int b    = blk >> 9;
    int s0   = sblk * 64;
    int h0   = hblk * 128;
    int w    = threadIdx.x >> 5;
    int lane = threadIdx.x & 31;

    // ---- phase 1: gumbel [128h x 64s] -> smem transposed ----
    {
        int c  = lane & 15;                  // float4 chunk along s
        int hr = lane >> 4;
        const float4* gb = (const float4*)(gumbel + ((size_t)(b * H_ + h0)) * S_ + s0);
#pragma unroll
        for (int a = 0; a < 8; ++a) {
            int hl = w * 16 + 2 * a + hr;    // local h: 0..127
            float4 g4 = __ldcs(&gb[(size_t)hl * (S_ / 4) + c]);
            int hq = hl >> 2, hk = hl & 3;
            int sw = (hq ^ c) << 2;
            sg[(4 * c + 0) * 128 + sw + hk] = g4.x;
            sg[(4 * c + 1) * 128 + sw + hk] = g4.y;
            sg[(4 * c + 2) * 128 + sw + hk] = g4.z;
            sg[(4 * c + 3) * 128 + sw + hk] = g4.w;
        }
    }
    __syncthreads();

    // ---- phase 2: warp w handles s in [w*8, w*8+8), lane = h-quad ----
    const float4* hbase = (const float4*)(hidden + ((size_t)b * S_ + s0 + w * 8) * H_ + h0) + lane;
    int rb = b * H_ + h0 + lane * 4;

    float4 xs[8];
#pragma unroll
    for (int j = 0; j < 8; ++j)
        xs[j] = __ldcs(&hbase[(size_t)j * (H_ / 4)]);

#pragma unroll
    for (int j = 0; j < 8; ++j) {
        int s = w * 8 + j;
        float4 g4 = sg4[s * 32 + (lane ^ (s >> 2))];
        flt_test(xs[j].x, g4.x, rb + 0);
        flt_test(xs[j].y, g4.y, rb + 1);
        flt_test(xs[j].z, g4.z, rb + 2);
        flt_test(xs[j].w, g4.w, rb + 3);
    }
}

// ---------------- 2: per-row top-8 over survivors (+ inline exact fallback) ----------------
__global__ __launch_bounds__(256) void k_select(const float* __restrict__ hidden,
                                                const float* __restrict__ gumbel) {
    int row  = (blockIdx.x * blockDim.x + threadIdx.x) >> 5;
    int lane = threadIdx.x & 31;
    if (row >= R_) return;

    const float NI = neg_inf();
    int cnt = g_cnt[row];
    if (lane == 0) g_cnt[row] = 0;           // restore for next graph replay

    float sum = 0.f;
    bool fast = false;

    if (cnt <= CAP) {
        // load survivors, compute EXACT scores (MUFU here is cheap: <=128/row)
        float sc0 = NI, sc1 = NI, sc2 = NI, sc3 = NI;
        float v0 = 0.f, v1 = 0.f, v2 = 0.f, v3 = 0.f;
        int base = row * CAP;
        if (lane      < cnt) { float2 c = g_buf[base + lane];      v0 = c.x; sc0 = fmaf(c.y, INV_LN2, __log2f(c.x)); }
        if (lane + 32 < cnt) { float2 c = g_buf[base + lane + 32]; v1 = c.x; sc1 = fmaf(c.y, INV_LN2, __log2f(c.x)); }
        if (lane + 64 < cnt) { float2 c = g_buf[base + lane + 64]; v2 = c.x; sc2 = fmaf(c.y, INV_LN2, __log2f(c.x)); }
        if (lane + 96 < cnt) { float2 c = g_buf[base + lane + 96]; v3 = c.x; sc3 = fmaf(c.y, INV_LN2, __log2f(c.x)); }

        // validity: need >=8 survivors with exact score clearly above threshold
        int npass = (sc0 > TAU_CHK) + (sc1 > TAU_CHK) + (sc2 > TAU_CHK) + (sc3 > TAU_CHK);
#pragma unroll
        for (int off = 16; off > 0; off >>= 1)
            npass += __shfl_xor_sync(0xffffffffu, npass, off);

        if (npass >= 8) {
            fast = true;
            for (int round = 0; round < 8; ++round) {
                float bs = sc0, bv = v0; int bi = 0;
                if (sc1 > bs) { bs = sc1; bv = v1; bi = 1; }
                if (sc2 > bs) { bs = sc2; bv = v2; bi = 2; }
                if (sc3 > bs) { bs = sc3; bv = v3; bi = 3; }
                float m = bs;
#pragma unroll
                for (int off = 16; off > 0; off >>= 1)
                    m = fmaxf(m, __shfl_xor_sync(0xffffffffu, m, off));
                unsigned ball = __ballot_sync(0xffffffffu, bs == m);
                int src = __ffs(ball) - 1;
                sum += __shfl_sync(0xffffffffu, bv, src);
                if (lane == src) {
                    if      (bi == 0) sc0 = NI;
                    else if (bi == 1) sc1 = NI;
                    else if (bi == 2) sc2 = NI;
                    else              sc3 = NI;
                }
            }
        }
    }

    if (!fast) {
        // exact fallback (rare; expected never): warp rescans the full row
        int b = row >> 10;
        int h = row & (H_ - 1);
        const float* hp = hidden + (size_t)b * S_ * H_ + h;
        const float* gp = gumbel + (size_t)row * S_;

        float lsc[8], lv[8];
#pragma unroll
        for (int j = 0; j < 8; ++j) { lsc[j] = NI; lv[j] = 0.f; }

        for (int s = lane; s < S_; s += 32) {
            float x = hp[(size_t)s * H_];
            float g = gp[s];
            float sc = (x > 0.f) ? fmaf(g, INV_LN2, __log2f(x)) : NI;
            if (sc > lsc[7]) {
                lsc[7] = sc; lv[7] = x;
#pragma unroll
                for (int j = 7; j > 0; --j) {
                    if (lsc[j] > lsc[j - 1]) {
                        float ts = lsc[j]; lsc[j] = lsc[j - 1]; lsc[j - 1] = ts;
                        float tv = lv[j];  lv[j]  = lv[j - 1];  lv[j - 1]  = tv;
                    }
                }
            }
        }
        sum = 0.f;
        int ptr = 0;
        for (int round = 0; round < 8; ++round) {
            float cand = NI, cval = 0.f;
#pragma unroll
            for (int j = 0; j < 8; ++j)
                if (j == ptr) { cand = lsc[j]; cval = lv[j]; }
            float m = cand;
#pragma unroll
            for (int off = 16; off > 0; off >>= 1)
                m = fmaxf(m, __shfl_xor_sync(0xffffffffu, m, off));
            unsigned ball = __ballot_sync(0xffffffffu, (cand == m) && (ptr < 8));
            if (ball == 0u) continue;        // remaining are -inf: contributes 0 (matches ref)
            int src = __ffs(ball) - 1;
            sum += __shfl_sync(0xffffffffu, cval, src);
            if (lane == src) ptr++;
        }
    }

    if (lane == 0) g_pooled[row] = sum;
}

// ---------------- 3: out = tanh(pooled @ W^T + bias) ----------------
__global__ __launch_bounds__(256) void k_gemm(const float* __restrict__ W,
                                              const float* __restrict__ bias,
                                              float* __restrict__ out) {
    int j = blockIdx.x;
    float acc[8];
#pragma unroll
    for (int bb = 0; bb < 8; ++bb) acc[bb] = 0.f;

    for (int h = threadIdx.x; h < H_; h += 256) {
        float wv = W[(size_t)j * H_ + h];
#pragma unroll
        for (int bb = 0; bb < 8; ++bb)
            acc[bb] += g_pooled[bb * H_ + h] * wv;
    }
#pragma unroll
    for (int bb = 0; bb < 8; ++bb)
#pragma unroll
        for (int off = 16; off > 0; off >>= 1)
            acc[bb] += __shfl_xor_sync(0xffffffffu, acc[bb], off);

    __shared__ float tot[8];
    if (threadIdx.x < 8) tot[threadIdx.x] = 0.f;
    __syncthreads();
    if ((threadIdx.x & 31) == 0) {
#pragma unroll
        for (int bb = 0; bb < 8; ++bb) atomicAdd(&tot[bb], acc[bb]);
    }
    __syncthreads();
    if (threadIdx.x < 8)
        out[threadIdx.x * H_ + j] = tanhf(tot[threadIdx.x] + bias[j]);
}

// ---------------- launch ----------------
extern "C" void kernel_launch(void* const* d_in, const int* in_sizes, int n_in,
                              void* d_out, int out_size) {
    const float* hidden = (const float*)d_in[0];
    const float* gumbel = (const float*)d_in[1];
    const float* W      = (const float*)d_in[2];
    const float* bias   = (const float*)d_in[3];
    float*       out    = (float*)d_out;
    (void)in_sizes; (void)n_in; (void)out_size;

    k_filter<<<4096, 256>>>(hidden, gumbel);
    k_select<<<1024, 256>>>(hidden, gumbel);
    k_gemm  <<<1024, 256>>>(W, bias, out);
}